// round 2
// baseline (speedup 1.0000x reference)
#include <cuda_runtime.h>
#include <math.h>

#define E_DIM 1024
#define H_DIM 2048
#define G3 6144            // 3*H
#define VOCAB 256
#define NBLK 148
#define NTHR 512
#define NWARPS (NTHR / 32)
#define TOTWARPS (NBLK * NWARPS)   // 2368

// ---------------- scratch (static device memory, no allocs) ----------------
__device__ float g_tbl[VOCAB * G3];      // W_ih @ emb[v] + b_ih, per vocab id (6.3 MB)
__device__ float g_rz[2][2 * H_DIM];     // sigmoid(r|z), double-buffered by step parity
__device__ float g_hhn[2][H_DIM];        // raw hh part of n-gate, double-buffered
__device__ unsigned g_barcnt = 0;
__device__ unsigned g_bargen = 0;

// ---------------- grid-wide barrier (148 co-resident CTAs) -----------------
__device__ __forceinline__ void grid_barrier() {
    __syncthreads();
    if (threadIdx.x == 0) {
        __threadfence();  // make this block's __stcg writes visible at L2
        volatile unsigned* vgen = &g_bargen;
        unsigned gen = *vgen;
        if (atomicAdd(&g_barcnt, 1u) == NBLK - 1) {
            atomicExch(&g_barcnt, 0u);
            __threadfence();
            atomicExch(&g_bargen, gen + 1);
        } else {
            while (*vgen == gen) { __nanosleep(64); }
        }
        __threadfence();
    }
    __syncthreads();
}

// ---------------- kernel 1: ih table GEMM  tbl[v][j] = W_ih[j,:]·emb[v,:] + b_ih[j]
__global__ __launch_bounds__(256) void tbl_kernel(
    const float* __restrict__ emb,     // [VOCAB, E]
    const float* __restrict__ w_ih,    // [G3, E]
    const float* __restrict__ b_ih)    // [G3]
{
    __shared__ float Es[32][33];
    __shared__ float Ws[64][33];
    const int tid = threadIdx.x;
    const int j0 = blockIdx.x * 64;    // 96 j-tiles
    const int v0 = blockIdx.y * 32;    // 8 v-tiles

    float acc[8] = {0.f, 0.f, 0.f, 0.f, 0.f, 0.f, 0.f, 0.f};
    const int jj = tid & 63;
    const int vb = (tid >> 6) * 8;

    for (int k0 = 0; k0 < E_DIM; k0 += 32) {
        __syncthreads();
        #pragma unroll
        for (int p = 0; p < 4; p++) {
            int idx = tid + p * 256;
            Es[idx >> 5][idx & 31] = emb[(size_t)(v0 + (idx >> 5)) * E_DIM + k0 + (idx & 31)];
        }
        #pragma unroll
        for (int p = 0; p < 8; p++) {
            int idx = tid + p * 256;
            Ws[idx >> 5][idx & 31] = w_ih[(size_t)(j0 + (idx >> 5)) * E_DIM + k0 + (idx & 31)];
        }
        __syncthreads();
        #pragma unroll
        for (int kk = 0; kk < 32; kk++) {
            float w = Ws[jj][kk];
            #pragma unroll
            for (int r = 0; r < 8; r++) acc[r] += w * Es[vb + r][kk];
        }
    }
    const int j = j0 + jj;
    const float bias = b_ih[j];
    #pragma unroll
    for (int r = 0; r < 8; r++)
        g_tbl[(size_t)(v0 + vb + r) * G3 + j] = acc[r] + bias;
}

// ---------------- kernel 2: persistent sequential GRU -----------------------
__global__ __launch_bounds__(NTHR, 1) void gru_kernel(
    const int*   __restrict__ x,
    const int*   __restrict__ lenp,
    const float* __restrict__ w_hh,    // [G3, H]
    const float* __restrict__ b_hh,    // [G3]
    const float* __restrict__ dec_emb, // [128, E]
    float*       __restrict__ out,     // [E + H]
    int n_x)
{
    __shared__ __align__(16) float hs[H_DIM];
    const int tid  = threadIdx.x;
    const int b    = blockIdx.x;
    const int lane = tid & 31;
    const int wid  = tid >> 5;

    for (int i = tid; i < H_DIM; i += NTHR) hs[i] = 0.f;

    int steps = lenp[0] + 1;
    if (steps > n_x) steps = n_x;

    // row assignment: warp (b, wid) owns rows j0, j1, (j2)
    const int j0 = b + NBLK * wid;          // < 2368  (always r/z region)
    const int j1 = j0 + TOTWARPS;           // < 4736
    const int j2 = j0 + 2 * TOTWARPS;       // valid iff < 6144 (always n region)
    const bool v2 = (j2 < G3);

    const float4* __restrict__ w0 = (const float4*)(w_hh + (size_t)j0 * H_DIM);
    const float4* __restrict__ w1 = (const float4*)(w_hh + (size_t)j1 * H_DIM);
    const float4* __restrict__ w2 = (const float4*)(w_hh + (size_t)(v2 ? j2 : j0) * H_DIM);
    const float4* h4 = (const float4*)hs;

    const float bh0 = b_hh[j0];
    const float bh1 = b_hh[j1];
    const float bh2 = v2 ? b_hh[j2] : 0.f;

    for (int t = 0; t < steps; ++t) {
        __syncthreads();   // hs (init or from previous update) visible to all warps
        const int xt = __ldg(&x[t]);
        const float* __restrict__ tbl = g_tbl + (size_t)xt * G3;
        const int p = t & 1;

        // ---- phase A: hh matvec for this warp's rows (W streamed from L2) ----
        float a0 = 0.f, a1 = 0.f, a2 = 0.f;
        #pragma unroll 4
        for (int k = lane; k < H_DIM / 4; k += 32) {
            float4 hv = h4[k];
            float4 q0 = w0[k];
            float4 q1 = w1[k];
            float4 q2 = w2[k];
            a0 += q0.x * hv.x + q0.y * hv.y + q0.z * hv.z + q0.w * hv.w;
            a1 += q1.x * hv.x + q1.y * hv.y + q1.z * hv.z + q1.w * hv.w;
            a2 += q2.x * hv.x + q2.y * hv.y + q2.z * hv.z + q2.w * hv.w;
        }
        #pragma unroll
        for (int o = 16; o; o >>= 1) {
            a0 += __shfl_xor_sync(0xffffffffu, a0, o);
            a1 += __shfl_xor_sync(0xffffffffu, a1, o);
            a2 += __shfl_xor_sync(0xffffffffu, a2, o);
        }
        if (lane == 0) {
            // j0 always in r/z region
            {
                float v = a0 + bh0 + __ldg(&tbl[j0]);
                __stcg(&g_rz[p][j0], 1.f / (1.f + expf(-v)));
            }
            if (j1 < 2 * H_DIM) {
                float v = a1 + bh1 + __ldg(&tbl[j1]);
                __stcg(&g_rz[p][j1], 1.f / (1.f + expf(-v)));
            } else {
                __stcg(&g_hhn[p][j1 - 2 * H_DIM], a1 + bh1);
            }
            if (v2) {
                __stcg(&g_hhn[p][j2 - 2 * H_DIM], a2 + bh2);
            }
        }

        grid_barrier();

        // ---- phase B: every block redundantly updates full h into its SMEM ----
        #pragma unroll
        for (int i = tid; i < H_DIM; i += NTHR) {
            float r    = __ldcg(&g_rz[p][i]);
            float z    = __ldcg(&g_rz[p][H_DIM + i]);
            float hh_n = __ldcg(&g_hhn[p][i]);
            float n    = tanhf(__ldg(&tbl[2 * H_DIM + i]) + r * hh_n);
            hs[i] = (1.f - z) * n + z * hs[i];
        }
        // loop-top __syncthreads orders hs writes before next phase A reads
    }

    __syncthreads();
    if (b == 0) {
        // output layout: dec_emb[2] (1024 floats) then h (2048 floats)
        for (int i = tid; i < E_DIM; i += NTHR) out[i] = dec_emb[2 * E_DIM + i];
        for (int i = tid; i < H_DIM; i += NTHR) out[E_DIM + i] = hs[i];
    }
}

// ---------------- launch ----------------------------------------------------
extern "C" void kernel_launch(void* const* d_in, const int* in_sizes, int n_in,
                              void* d_out, int out_size) {
    const int*   x       = (const int*)d_in[0];
    const int*   lenp    = (const int*)d_in[1];
    const float* enc_emb = (const float*)d_in[2];
    const float* w_ih    = (const float*)d_in[3];
    const float* w_hh    = (const float*)d_in[4];
    const float* b_ih    = (const float*)d_in[5];
    const float* b_hh    = (const float*)d_in[6];
    const float* dec_emb = (const float*)d_in[7];
    float* out = (float*)d_out;
    const int n_x = in_sizes[0];

    dim3 tgrid(G3 / 64, VOCAB / 32);   // 96 x 8
    tbl_kernel<<<tgrid, 256>>>(enc_emb, w_ih, b_ih);
    gru_kernel<<<NBLK, NTHR>>>(x, lenp, w_hh, b_hh, dec_emb, out, n_x);
}

// round 3
// speedup vs baseline: 1.0936x; 1.0936x over previous
#include <cuda_runtime.h>
#include <math.h>

#define E_DIM 1024
#define H_DIM 2048
#define G3 6144            // 3*H
#define VOCAB 256
#define NBLK 148
#define NTHR 512
#define NWARPS (NTHR / 32)
#define TOTWARPS (NBLK * NWARPS)   // 2368

// ---------------- scratch (static device memory, no allocs) ----------------
__device__ float g_tbl[VOCAB * G3];      // W_ih @ emb[v] + b_ih, per vocab id (6.3 MB)
__device__ float g_h[2][H_DIM];          // hidden state, double-buffered by step parity
__device__ unsigned g_barcnt = 0;
__device__ unsigned g_bargen = 0;

// ---------------- grid-wide barrier (148 co-resident CTAs) -----------------
__device__ __forceinline__ void grid_barrier() {
    __syncthreads();
    if (threadIdx.x == 0) {
        __threadfence();  // make this block's __stcg writes visible at L2
        volatile unsigned* vgen = &g_bargen;
        unsigned gen = *vgen;
        if (atomicAdd(&g_barcnt, 1u) == NBLK - 1) {
            atomicExch(&g_barcnt, 0u);
            __threadfence();
            atomicExch(&g_bargen, gen + 1);
        } else {
            while (*vgen == gen) { __nanosleep(64); }
        }
        __threadfence();
    }
    __syncthreads();
}

// ---------------- kernel 1: ih table GEMM  tbl[v][j] = W_ih[j,:]·emb[v,:] + b_ih[j]
__global__ __launch_bounds__(256) void tbl_kernel(
    const float* __restrict__ emb,     // [VOCAB, E]
    const float* __restrict__ w_ih,    // [G3, E]
    const float* __restrict__ b_ih)    // [G3]
{
    __shared__ float Es[32][33];
    __shared__ float Ws[64][33];
    const int tid = threadIdx.x;
    const int j0 = blockIdx.x * 64;    // 96 j-tiles
    const int v0 = blockIdx.y * 32;    // 8 v-tiles

    float acc[8] = {0.f, 0.f, 0.f, 0.f, 0.f, 0.f, 0.f, 0.f};
    const int jj = tid & 63;
    const int vb = (tid >> 6) * 8;

    for (int k0 = 0; k0 < E_DIM; k0 += 32) {
        __syncthreads();
        #pragma unroll
        for (int p = 0; p < 4; p++) {
            int idx = tid + p * 256;
            Es[idx >> 5][idx & 31] = emb[(size_t)(v0 + (idx >> 5)) * E_DIM + k0 + (idx & 31)];
        }
        #pragma unroll
        for (int p = 0; p < 8; p++) {
            int idx = tid + p * 256;
            Ws[idx >> 5][idx & 31] = w_ih[(size_t)(j0 + (idx >> 5)) * E_DIM + k0 + (idx & 31)];
        }
        __syncthreads();
        #pragma unroll
        for (int kk = 0; kk < 32; kk++) {
            float w = Ws[jj][kk];
            #pragma unroll
            for (int r = 0; r < 8; r++) acc[r] += w * Es[vb + r][kk];
        }
    }
    const int j = j0 + jj;
    const float bias = b_ih[j];
    #pragma unroll
    for (int r = 0; r < 8; r++)
        g_tbl[(size_t)(v0 + vb + r) * G3 + j] = acc[r] + bias;
}

// ---------------- kernel 2: persistent sequential GRU -----------------------
// Warp (b, wid) owns hidden unit jw = wid*NBLK + b (if jw < H_DIM), computing
// all three gate rows {jw, jw+H, jw+2H} so the full cell update for unit jw
// completes locally in lane 0. Phase B is then just a broadcast copy of the
// new h vector into each block's SMEM.
__global__ __launch_bounds__(NTHR, 1) void gru_kernel(
    const int*   __restrict__ x,
    const int*   __restrict__ lenp,
    const float* __restrict__ w_hh,    // [G3, H]
    const float* __restrict__ b_hh,    // [G3]
    const float* __restrict__ dec_emb, // [128, E]
    float*       __restrict__ out,     // [E + H]
    int n_x)
{
    __shared__ __align__(16) float hs[H_DIM];
    const int tid  = threadIdx.x;
    const int b    = blockIdx.x;
    const int lane = tid & 31;
    const int wid  = tid >> 5;

    for (int i = tid; i < H_DIM; i += NTHR) hs[i] = 0.f;

    int steps = lenp[0] + 1;
    if (steps > n_x) steps = n_x;

    // hidden-unit assignment: warp owns unit jw -> rows jw (r), jw+H (z), jw+2H (n)
    const int jw = wid * NBLK + b;
    const bool active = (jw < H_DIM);
    const int jsafe = active ? jw : 0;

    const float4* __restrict__ w0 = (const float4*)(w_hh + (size_t)jsafe * H_DIM);
    const float4* __restrict__ w1 = (const float4*)(w_hh + (size_t)(jsafe + H_DIM) * H_DIM);
    const float4* __restrict__ w2 = (const float4*)(w_hh + (size_t)(jsafe + 2 * H_DIM) * H_DIM);
    const float4* h4 = (const float4*)hs;

    const float bh0 = b_hh[jsafe];
    const float bh1 = b_hh[jsafe + H_DIM];
    const float bh2 = b_hh[jsafe + 2 * H_DIM];

    for (int t = 0; t < steps; ++t) {
        __syncthreads();   // hs (init or previous copy) visible to all warps
        const int p = t & 1;

        if (active) {
            const int xt = __ldg(&x[t]);
            const float* __restrict__ tbl = g_tbl + (size_t)xt * G3;

            // hoist lane-0's table reads above the matvec so their L2 latency
            // hides under the weight stream
            float ih_r = 0.f, ih_z = 0.f, ih_n = 0.f;
            if (lane == 0) {
                ih_r = __ldg(&tbl[jw]);
                ih_z = __ldg(&tbl[jw + H_DIM]);
                ih_n = __ldg(&tbl[jw + 2 * H_DIM]);
            }

            // ---- phase A: three row dot-products, W streamed from L2 ----
            float a0 = 0.f, a1 = 0.f, a2 = 0.f;
            #pragma unroll 4
            for (int k = lane; k < H_DIM / 4; k += 32) {
                float4 hv = h4[k];
                float4 q0 = w0[k];
                float4 q1 = w1[k];
                float4 q2 = w2[k];
                a0 += q0.x * hv.x + q0.y * hv.y + q0.z * hv.z + q0.w * hv.w;
                a1 += q1.x * hv.x + q1.y * hv.y + q1.z * hv.z + q1.w * hv.w;
                a2 += q2.x * hv.x + q2.y * hv.y + q2.z * hv.z + q2.w * hv.w;
            }
            #pragma unroll
            for (int o = 16; o; o >>= 1) {
                a0 += __shfl_xor_sync(0xffffffffu, a0, o);
                a1 += __shfl_xor_sync(0xffffffffu, a1, o);
                a2 += __shfl_xor_sync(0xffffffffu, a2, o);
            }
            if (lane == 0) {
                float r   = 1.f / (1.f + expf(-(a0 + bh0 + ih_r)));
                float z   = 1.f / (1.f + expf(-(a1 + bh1 + ih_z)));
                float n   = tanhf(ih_n + r * (a2 + bh2));
                float hold = hs[jw];
                __stcg(&g_h[p][jw], (1.f - z) * n + z * hold);
            }
        }

        grid_barrier();

        // ---- phase B: copy new h into this block's SMEM (1 float4/thread) ----
        {
            float4 v = __ldcg(((const float4*)g_h[p]) + tid);
            ((float4*)hs)[tid] = v;
        }
        // loop-top __syncthreads orders hs writes before next phase A reads
    }

    __syncthreads();
    if (b == 0) {
        // output layout: dec_emb[2] (1024 floats) then h (2048 floats)
        for (int i = tid; i < E_DIM; i += NTHR) out[i] = dec_emb[2 * E_DIM + i];
        for (int i = tid; i < H_DIM; i += NTHR) out[E_DIM + i] = hs[i];
    }
}

// ---------------- launch ----------------------------------------------------
extern "C" void kernel_launch(void* const* d_in, const int* in_sizes, int n_in,
                              void* d_out, int out_size) {
    const int*   x       = (const int*)d_in[0];
    const int*   lenp    = (const int*)d_in[1];
    const float* enc_emb = (const float*)d_in[2];
    const float* w_ih    = (const float*)d_in[3];
    const float* w_hh    = (const float*)d_in[4];
    const float* b_ih    = (const float*)d_in[5];
    const float* b_hh    = (const float*)d_in[6];
    const float* dec_emb = (const float*)d_in[7];
    float* out = (float*)d_out;
    const int n_x = in_sizes[0];

    dim3 tgrid(G3 / 64, VOCAB / 32);   // 96 x 8
    tbl_kernel<<<tgrid, 256>>>(enc_emb, w_ih, b_ih);
    gru_kernel<<<NBLK, NTHR>>>(x, lenp, w_hh, b_hh, dec_emb, out, n_x);
}

// round 4
// speedup vs baseline: 1.1344x; 1.0373x over previous
#include <cuda_runtime.h>
#include <cuda_fp16.h>
#include <math.h>

#define E_DIM 1024
#define H_DIM 2048
#define G3 6144            // 3*H
#define VOCAB 256
#define NBLK 148
#define NTHR 512

// units per block: blocks [0,124) own 14 units, [124,148) own 13  (124*14+24*13=2048)
#define NU_MAX 14
#define NROWS_MAX (3 * NU_MAX)   // 42

// SMEM layout (dynamic): fp16 weights [42][2048] | hs[2048] fp32 | a_loc[48]
#define WS_BYTES (NROWS_MAX * H_DIM * 2)          // 172032
#define HS_OFF   WS_BYTES
#define ALOC_OFF (WS_BYTES + H_DIM * 4)
#define SMEM_TOTAL (ALOC_OFF + 64 * 4)            // 180480

// ---------------- scratch (static device memory, no allocs) ----------------
__device__ float g_tbl[VOCAB * G3];      // W_ih@emb[v] + b_ih (+b_hh for r,z rows)
__device__ float g_h[2][H_DIM];          // hidden state, double-buffered
__device__ unsigned g_cnt_sub[16 * 32];  // 16 sub-counters, 128B apart
__device__ unsigned g_cnt_top = 0;
__device__ unsigned g_bargen = 0;

// ---------------- two-level grid barrier (148 co-resident CTAs) -------------
__device__ __forceinline__ void grid_barrier(int b) {
    __syncthreads();
    if (threadIdx.x == 0) {
        __threadfence();
        volatile unsigned* vgen = &g_bargen;
        unsigned gen = *vgen;
        const int grp = b & 15;
        const int gsize = (grp < 4) ? 10 : 9;   // 4*10 + 12*9 = 148
        if (atomicAdd(&g_cnt_sub[grp * 32], 1u) == (unsigned)(gsize - 1)) {
            atomicExch(&g_cnt_sub[grp * 32], 0u);
            __threadfence();
            if (atomicAdd(&g_cnt_top, 1u) == 15u) {
                atomicExch(&g_cnt_top, 0u);
                __threadfence();
                atomicExch(&g_bargen, gen + 1);
            }
        }
        while (*vgen == gen) { __nanosleep(32); }
        __threadfence();
    }
    __syncthreads();
}

// ---------------- kernel 1: ih table GEMM + state init ----------------------
// tbl[v][j] = W_ih[j,:]·emb[v,:] + b_ih[j] + (j < 2H ? b_hh[j] : 0)
__global__ __launch_bounds__(256) void tbl_kernel(
    const float* __restrict__ emb,     // [VOCAB, E]
    const float* __restrict__ w_ih,    // [G3, E]
    const float* __restrict__ b_ih,    // [G3]
    const float* __restrict__ b_hh)    // [G3]
{
    __shared__ float Es[32][33];
    __shared__ float Ws[64][33];
    const int tid = threadIdx.x;
    const int j0 = blockIdx.x * 64;
    const int v0 = blockIdx.y * 32;

    if (blockIdx.x == 0 && blockIdx.y == 0) {  // zero h double-buffer each launch
        for (int i = tid; i < 2 * H_DIM; i += 256) ((float*)g_h)[i] = 0.f;
    }

    float acc[8] = {0.f, 0.f, 0.f, 0.f, 0.f, 0.f, 0.f, 0.f};
    const int jj = tid & 63;
    const int vb = (tid >> 6) * 8;

    for (int k0 = 0; k0 < E_DIM; k0 += 32) {
        __syncthreads();
        #pragma unroll
        for (int p = 0; p < 4; p++) {
            int idx = tid + p * 256;
            Es[idx >> 5][idx & 31] = emb[(size_t)(v0 + (idx >> 5)) * E_DIM + k0 + (idx & 31)];
        }
        #pragma unroll
        for (int p = 0; p < 8; p++) {
            int idx = tid + p * 256;
            Ws[idx >> 5][idx & 31] = w_ih[(size_t)(j0 + (idx >> 5)) * E_DIM + k0 + (idx & 31)];
        }
        __syncthreads();
        #pragma unroll
        for (int kk = 0; kk < 32; kk++) {
            float w = Ws[jj][kk];
            #pragma unroll
            for (int r = 0; r < 8; r++) acc[r] += w * Es[vb + r][kk];
        }
    }
    const int j = j0 + jj;
    float bias = b_ih[j] + ((j < 2 * H_DIM) ? b_hh[j] : 0.f);
    #pragma unroll
    for (int r = 0; r < 8; r++)
        g_tbl[(size_t)(v0 + vb + r) * G3 + j] = acc[r] + bias;
}

// ---------------- kernel 2: persistent GRU, fp16 weights in SMEM ------------
__global__ void __launch_bounds__(NTHR, 1) gru_kernel(
    const int*   __restrict__ x,
    const int*   __restrict__ lenp,
    const float* __restrict__ w_hh,    // [G3, H] fp32
    const float* __restrict__ b_hh,    // [G3]
    const float* __restrict__ dec_emb, // [128, E]
    float*       __restrict__ out,     // [E + H]
    int n_x)
{
    extern __shared__ __align__(16) unsigned char smem_raw[];
    __half* ws   = (__half*)smem_raw;
    float*  hs   = (float*)(smem_raw + HS_OFF);
    float*  a_loc = (float*)(smem_raw + ALOC_OFF);

    const int tid  = threadIdx.x;
    const int b    = blockIdx.x;
    const int lane = tid & 31;
    const int wid  = tid >> 5;

    const int u0 = (b < 124) ? b * 14 : 1736 + (b - 124) * 13;
    const int nu = (b < 124) ? 14 : 13;
    const int nrows = 3 * nu;

    // ---- prologue: convert this block's weight rows fp32 -> fp16 SMEM ----
    // row layout: local row lr = g*nu + i  <->  global row g*H + u0 + i
    for (int lr = 0; lr < nrows; lr++) {
        int g = lr / nu, i = lr - g * nu;
        int rg = g * H_DIM + u0 + i;
        float4 v = __ldcs(((const float4*)w_hh) + (size_t)rg * (H_DIM / 4) + tid);
        __half2* dst = (__half2*)(ws + lr * H_DIM);
        dst[tid * 2]     = __floats2half2_rn(v.x, v.y);
        dst[tid * 2 + 1] = __floats2half2_rn(v.z, v.w);
    }

    // per-unit invariants for tail threads
    float bhn = 0.f;
    if (tid < nu) bhn = __ldg(&b_hh[2 * H_DIM + u0 + tid]);

    int steps = lenp[0] + 1;
    if (steps > n_x) steps = n_x;

    for (int t = 0; t < steps; ++t) {
        const int cur = t & 1, prev = cur ^ 1;

        // ---- load h_prev: block-wide copy into SMEM + tail prefetches ----
        {
            float4 v = __ldcg(((const float4*)g_h[prev]) + tid);
            ((float4*)hs)[tid] = v;
        }
        float ih_r = 0.f, ih_z = 0.f, ih_n = 0.f, hold = 0.f;
        if (tid < nu) {
            const int xt = __ldg(&x[t]);
            const float* __restrict__ tbl = g_tbl + (size_t)xt * G3;
            const int u = u0 + tid;
            ih_r = __ldg(&tbl[u]);
            ih_z = __ldg(&tbl[u + H_DIM]);
            ih_n = __ldg(&tbl[u + 2 * H_DIM]);
            hold = __ldcg(&g_h[prev][u]);
        }
        __syncthreads();

        // ---- fill h registers: lane holds k in {c*256 + lane*8 .. +7} ----
        float4 hr0[8], hr1[8];
        #pragma unroll
        for (int c = 0; c < 8; c++) {
            hr0[c] = ((const float4*)hs)[c * 64 + lane * 2];
            hr1[c] = ((const float4*)hs)[c * 64 + lane * 2 + 1];
        }

        // ---- matvec: warp does rows wid, wid+16, wid+32 ----
        #pragma unroll
        for (int rr = 0; rr < 3; rr++) {
            const int lr = wid + rr * 16;
            if (lr < nrows) {
                const uint4* wrow = (const uint4*)(ws + lr * H_DIM);
                float a0 = 0.f, a1 = 0.f, a2 = 0.f, a3 = 0.f;
                #pragma unroll
                for (int c = 0; c < 8; c++) {
                    uint4 wv = wrow[c * 32 + lane];
                    float2 f0 = __half22float2(*(__half2*)&wv.x);
                    float2 f1 = __half22float2(*(__half2*)&wv.y);
                    float2 f2 = __half22float2(*(__half2*)&wv.z);
                    float2 f3 = __half22float2(*(__half2*)&wv.w);
                    a0 = fmaf(f0.x, hr0[c].x, a0);
                    a1 = fmaf(f0.y, hr0[c].y, a1);
                    a2 = fmaf(f1.x, hr0[c].z, a2);
                    a3 = fmaf(f1.y, hr0[c].w, a3);
                    a0 = fmaf(f2.x, hr1[c].x, a0);
                    a1 = fmaf(f2.y, hr1[c].y, a1);
                    a2 = fmaf(f3.x, hr1[c].z, a2);
                    a3 = fmaf(f3.y, hr1[c].w, a3);
                }
                float a = (a0 + a1) + (a2 + a3);
                #pragma unroll
                for (int o = 16; o; o >>= 1) a += __shfl_xor_sync(0xffffffffu, a, o);
                if (lane == 0) a_loc[lr] = a;
            }
        }
        __syncthreads();

        // ---- tail: one thread per unit completes the GRU cell ----
        if (tid < nu) {
            float ar = a_loc[tid];
            float az = a_loc[nu + tid];
            float an = a_loc[2 * nu + tid];
            float r = 1.f / (1.f + __expf(-(ar + ih_r)));   // biases folded in tbl
            float z = 1.f / (1.f + __expf(-(az + ih_z)));
            float n = tanhf(ih_n + r * (an + bhn));
            __stcg(&g_h[cur][u0 + tid], (1.f - z) * n + z * hold);
        }

        grid_barrier(b);
    }

    if (b == 0) {
        const int last = (steps - 1) & 1;
        for (int i = tid; i < E_DIM; i += NTHR) out[i] = dec_emb[2 * E_DIM + i];
        for (int i = tid; i < H_DIM; i += NTHR) out[E_DIM + i] = __ldcg(&g_h[last][i]);
    }
}

// ---------------- launch ----------------------------------------------------
extern "C" void kernel_launch(void* const* d_in, const int* in_sizes, int n_in,
                              void* d_out, int out_size) {
    const int*   x       = (const int*)d_in[0];
    const int*   lenp    = (const int*)d_in[1];
    const float* enc_emb = (const float*)d_in[2];
    const float* w_ih    = (const float*)d_in[3];
    const float* w_hh    = (const float*)d_in[4];
    const float* b_ih    = (const float*)d_in[5];
    const float* b_hh    = (const float*)d_in[6];
    const float* dec_emb = (const float*)d_in[7];
    float* out = (float*)d_out;
    const int n_x = in_sizes[0];

    static int attr_set = 0;
    if (!attr_set) {
        cudaFuncSetAttribute(gru_kernel, cudaFuncAttributeMaxDynamicSharedMemorySize,
                             SMEM_TOTAL);
        attr_set = 1;
    }

    dim3 tgrid(G3 / 64, VOCAB / 32);   // 96 x 8
    tbl_kernel<<<tgrid, 256>>>(enc_emb, w_ih, b_ih, b_hh);
    gru_kernel<<<NBLK, NTHR, SMEM_TOTAL>>>(x, lenp, w_hh, b_hh, dec_emb, out, n_x);
}

// round 5
// speedup vs baseline: 1.9076x; 1.6816x over previous
#include <cuda_runtime.h>
#include <cuda_fp16.h>
#include <math.h>

#define E_DIM 1024
#define H_DIM 2048
#define G3 6144            // 3*H
#define VOCAB 256
#define NBLK 148
#define NTHR 512
#define UPB 14             // max hidden units per block (148*14 >= 2048)
#define NROWS_MAX (3 * UPB)   // 42

// SMEM: fp16 weights [42][2048] | hs[2048] fp32
#define WS_BYTES (NROWS_MAX * H_DIM * 2)   // 172032
#define HS_OFF   WS_BYTES
#define SMEM_TOTAL (HS_OFF + H_DIM * 4)    // 180224

// ---------------- scratch (static device memory, no allocs) ----------------
__device__ float g_tbl[VOCAB * G3];   // W_ih@emb[v] + b_ih (+b_hh folded for r,z)
__device__ float g_h[2][H_DIM];       // hidden state, double-buffered
__device__ unsigned g_cnt;            // monotonic phased barrier counter

// ---------------- barrier primitives ----------------------------------------
__device__ __forceinline__ unsigned ld_acq(const unsigned* p) {
    unsigned v;
    asm volatile("ld.acquire.gpu.global.b32 %0, [%1];" : "=r"(v) : "l"(p) : "memory");
    return v;
}
__device__ __forceinline__ void red_rel_add1(unsigned* p) {
    asm volatile("red.release.gpu.global.add.u32 [%0], %1;" :: "l"(p), "r"(1u) : "memory");
}

// ---------------- kernel 1: ih table GEMM + state/counter init --------------
__global__ __launch_bounds__(256) void tbl_kernel(
    const float* __restrict__ emb,     // [VOCAB, E]
    const float* __restrict__ w_ih,    // [G3, E]
    const float* __restrict__ b_ih,    // [G3]
    const float* __restrict__ b_hh)    // [G3]
{
    __shared__ float Es[32][33];
    __shared__ float Ws[64][33];
    const int tid = threadIdx.x;
    const int j0 = blockIdx.x * 64;
    const int v0 = blockIdx.y * 32;

    if (blockIdx.x == 0 && blockIdx.y == 0) {
        for (int i = tid; i < 2 * H_DIM; i += 256) ((float*)g_h)[i] = 0.f;
        if (tid == 0) g_cnt = 0u;
    }

    float acc[8] = {0.f, 0.f, 0.f, 0.f, 0.f, 0.f, 0.f, 0.f};
    const int jj = tid & 63;
    const int vb = (tid >> 6) * 8;

    for (int k0 = 0; k0 < E_DIM; k0 += 32) {
        __syncthreads();
        #pragma unroll
        for (int p = 0; p < 4; p++) {
            int idx = tid + p * 256;
            Es[idx >> 5][idx & 31] = emb[(size_t)(v0 + (idx >> 5)) * E_DIM + k0 + (idx & 31)];
        }
        #pragma unroll
        for (int p = 0; p < 8; p++) {
            int idx = tid + p * 256;
            Ws[idx >> 5][idx & 31] = w_ih[(size_t)(j0 + (idx >> 5)) * E_DIM + k0 + (idx & 31)];
        }
        __syncthreads();
        #pragma unroll
        for (int kk = 0; kk < 32; kk++) {
            float w = Ws[jj][kk];
            #pragma unroll
            for (int r = 0; r < 8; r++) acc[r] += w * Es[vb + r][kk];
        }
    }
    const int j = j0 + jj;
    float bias = b_ih[j] + ((j < 2 * H_DIM) ? b_hh[j] : 0.f);
    #pragma unroll
    for (int r = 0; r < 8; r++)
        g_tbl[(size_t)(v0 + vb + r) * G3 + j] = acc[r] + bias;
}

// ---------------- fp16x8 dot helper -----------------------------------------
__device__ __forceinline__ void dot8(uint4 q, float4 h0, float4 h1,
                                     float& a, float& b) {
    float2 f0 = __half22float2(*(__half2*)&q.x);
    float2 f1 = __half22float2(*(__half2*)&q.y);
    float2 f2 = __half22float2(*(__half2*)&q.z);
    float2 f3 = __half22float2(*(__half2*)&q.w);
    a = fmaf(f0.x, h0.x, a);  b = fmaf(f0.y, h0.y, b);
    a = fmaf(f1.x, h0.z, a);  b = fmaf(f1.y, h0.w, b);
    a = fmaf(f2.x, h1.x, a);  b = fmaf(f2.y, h1.y, b);
    a = fmaf(f3.x, h1.z, a);  b = fmaf(f3.y, h1.w, b);
}

// ---------------- kernel 2: persistent GRU, fp16 weights in SMEM ------------
// Warp w of block b owns hidden unit u = b*14 + w (if < 2048): all three gate
// rows live in this block's SMEM as local rows {3w, 3w+1, 3w+2}. Lane 0
// finishes the whole GRU cell for its unit. Grid sync = monotonic counter.
__global__ void __launch_bounds__(NTHR, 1) gru_kernel(
    const int*   __restrict__ x,
    const int*   __restrict__ lenp,
    const float* __restrict__ w_hh,    // [G3, H] fp32
    const float* __restrict__ b_hh,    // [G3]
    const float* __restrict__ dec_emb, // [128, E]
    float*       __restrict__ out,     // [E + H]
    int n_x)
{
    extern __shared__ __align__(16) unsigned char smem_raw[];
    __half* ws = (__half*)smem_raw;
    float*  hs = (float*)(smem_raw + HS_OFF);

    const int tid  = threadIdx.x;
    const int b    = blockIdx.x;
    const int lane = tid & 31;
    const int wid  = tid >> 5;

    const int u0 = b * UPB;
    int nu = H_DIM - u0;
    if (nu > UPB) nu = UPB;
    if (nu < 0) nu = 0;

    // ---- prologue: convert this block's rows fp32 -> fp16 SMEM -------------
    // local row 3*w + g  <->  global row g*H + u0 + w
    for (int lr = 0; lr < 3 * nu; lr++) {
        int w = lr / 3, g = lr - 3 * w;
        int row = g * H_DIM + u0 + w;
        float4 v = __ldcs(((const float4*)w_hh) + (size_t)row * (H_DIM / 4) + tid);
        __half2* dst = (__half2*)(ws + lr * H_DIM);
        dst[tid * 2]     = __floats2half2_rn(v.x, v.y);
        dst[tid * 2 + 1] = __floats2half2_rn(v.z, v.w);
    }

    const bool writer = (wid < nu);
    const int u = u0 + wid;
    float bhn = 0.f;
    if (writer && lane == 0) bhn = __ldg(&b_hh[2 * H_DIM + u]);

    int steps = lenp[0] + 1;
    if (steps > n_x) steps = n_x;

    unsigned target = 0;

    for (int t = 0; t < steps; ++t) {
        // ---- wait: all blocks finished step t-1 (h(t) complete) ----
        if (tid == 0) {
            while (ld_acq(&g_cnt) < target) { }
        }
        __syncthreads();

        const int prev = t & 1;

        // ---- stage h(t) into SMEM (512 threads x float4 = 2048 floats) ----
        {
            float4 v = __ldcg(((const float4*)g_h[prev]) + tid);
            ((float4*)hs)[tid] = v;
        }
        // hoisted per-unit table reads (L2 latency hides under matvec)
        float ih_r = 0.f, ih_z = 0.f, ih_n = 0.f;
        if (writer && lane == 0) {
            const int xt = __ldg(&x[t]);
            const float* __restrict__ tbl = g_tbl + (size_t)xt * G3;
            ih_r = __ldg(&tbl[u]);
            ih_z = __ldg(&tbl[u + H_DIM]);
            ih_n = __ldg(&tbl[u + 2 * H_DIM]);
        }
        __syncthreads();

        if (writer) {
            const uint4* w0 = (const uint4*)(ws + (size_t)(3 * wid)     * H_DIM);
            const uint4* w1 = (const uint4*)(ws + (size_t)(3 * wid + 1) * H_DIM);
            const uint4* w2 = (const uint4*)(ws + (size_t)(3 * wid + 2) * H_DIM);
            const float4* hs4 = (const float4*)hs;

            float a0 = 0.f, a1 = 0.f, a2 = 0.f;
            float c0 = 0.f, c1 = 0.f, c2 = 0.f;
            #pragma unroll
            for (int c = 0; c < 8; c++) {
                float4 h0 = hs4[c * 64 + lane * 2];
                float4 h1 = hs4[c * 64 + lane * 2 + 1];
                uint4 q0 = w0[c * 32 + lane];
                uint4 q1 = w1[c * 32 + lane];
                uint4 q2 = w2[c * 32 + lane];
                dot8(q0, h0, h1, a0, c0);
                dot8(q1, h0, h1, a1, c1);
                dot8(q2, h0, h1, a2, c2);
            }
            a0 += c0; a1 += c1; a2 += c2;
            #pragma unroll
            for (int o = 16; o; o >>= 1) {
                a0 += __shfl_xor_sync(0xffffffffu, a0, o);
                a1 += __shfl_xor_sync(0xffffffffu, a1, o);
                a2 += __shfl_xor_sync(0xffffffffu, a2, o);
            }
            if (lane == 0) {
                float r = 1.f / (1.f + __expf(-(a0 + ih_r)));  // biases folded into tbl
                float z = 1.f / (1.f + __expf(-(a1 + ih_z)));
                float n = tanhf(ih_n + r * (a2 + bhn));
                float hold = hs[u];
                __stcg(&g_h[prev ^ 1][u], (1.f - z) * n + z * hold);
            }
        }
        __syncthreads();

        // ---- arrive: one release-RED per block ----
        if (tid == 0) red_rel_add1(&g_cnt);
        target += NBLK;
    }

    if (b == 0) {
        if (tid == 0) {
            while (ld_acq(&g_cnt) < target) { }   // all blocks' final writes visible
        }
        __syncthreads();
        const int last = steps & 1;
        for (int i = tid; i < E_DIM; i += NTHR) out[i] = dec_emb[2 * E_DIM + i];
        for (int i = tid; i < H_DIM; i += NTHR) out[E_DIM + i] = __ldcg(&g_h[last][i]);
    }
}

// ---------------- launch ----------------------------------------------------
extern "C" void kernel_launch(void* const* d_in, const int* in_sizes, int n_in,
                              void* d_out, int out_size) {
    const int*   x       = (const int*)d_in[0];
    const int*   lenp    = (const int*)d_in[1];
    const float* enc_emb = (const float*)d_in[2];
    const float* w_ih    = (const float*)d_in[3];
    const float* w_hh    = (const float*)d_in[4];
    const float* b_ih    = (const float*)d_in[5];
    const float* b_hh    = (const float*)d_in[6];
    const float* dec_emb = (const float*)d_in[7];
    float* out = (float*)d_out;
    const int n_x = in_sizes[0];

    static int attr_set = 0;
    if (!attr_set) {
        cudaFuncSetAttribute(gru_kernel, cudaFuncAttributeMaxDynamicSharedMemorySize,
                             SMEM_TOTAL);
        attr_set = 1;
    }

    dim3 tgrid(G3 / 64, VOCAB / 32);   // 96 x 8
    tbl_kernel<<<tgrid, 256>>>(enc_emb, w_ih, b_ih, b_hh);
    gru_kernel<<<NBLK, NTHR, SMEM_TOTAL>>>(x, lenp, w_hh, b_hh, dec_emb, out, n_x);
}

// round 6
// speedup vs baseline: 2.0701x; 1.0852x over previous
#include <cuda_runtime.h>
#include <cuda_fp16.h>
#include <math.h>

#define E_DIM 1024
#define H_DIM 2048
#define G3 6144            // 3*H
#define VOCAB 256
#define NBLK 148
#define NTHR 512
#define UPB 14             // hidden units per block (148*14 >= 2048)
#define NROWS_MAX (3 * UPB)   // 42

// SMEM: high-k half of weights [42][1024] fp16 | hs[2048] fp32
#define WS2_HALFS 1024
#define WS2_BYTES (NROWS_MAX * WS2_HALFS * 2)   // 86016
#define HS_OFF WS2_BYTES
#define SMEM_TOTAL (HS_OFF + H_DIM * 4)         // 94208

// ---------------- scratch (static device memory, no allocs) ----------------
__device__ float g_tbl[VOCAB * G3];   // W_ih@emb[v] + b_ih (+b_hh folded for r,z)
__device__ float g_h[2][H_DIM];       // hidden state, double-buffered
__device__ unsigned g_cnt;            // monotonic phased barrier counter

// ---------------- barrier primitives ----------------------------------------
__device__ __forceinline__ unsigned ld_acq(const unsigned* p) {
    unsigned v;
    asm volatile("ld.acquire.gpu.global.b32 %0, [%1];" : "=r"(v) : "l"(p) : "memory");
    return v;
}
__device__ __forceinline__ void red_rel_add1(unsigned* p) {
    asm volatile("red.release.gpu.global.add.u32 [%0], %1;" :: "l"(p), "r"(1u) : "memory");
}

// ---------------- packed f32x2 helpers ---------------------------------------
__device__ __forceinline__ unsigned long long pk(float x, float y) {
    unsigned long long r;
    asm("mov.b64 %0, {%1, %2};" : "=l"(r) : "f"(x), "f"(y));
    return r;
}
__device__ __forceinline__ float2 unpk(unsigned long long v) {
    float2 r;
    asm("mov.b64 {%0, %1}, %2;" : "=f"(r.x), "=f"(r.y) : "l"(v));
    return r;
}
__device__ __forceinline__ void fma2(unsigned long long& d,
                                     unsigned long long a, unsigned long long b) {
    asm("fma.rn.f32x2 %0, %1, %2, %0;" : "+l"(d) : "l"(a), "l"(b));
}
// 8 fp16 weights (uint4) dotted against 8 fp32 h values (4 packed f32x2)
__device__ __forceinline__ void dotq(uint4 w,
    unsigned long long hp0, unsigned long long hp1,
    unsigned long long hp2, unsigned long long hp3,
    unsigned long long& aA, unsigned long long& aB) {
    float2 f0 = __half22float2(*(__half2*)&w.x);
    float2 f1 = __half22float2(*(__half2*)&w.y);
    float2 f2 = __half22float2(*(__half2*)&w.z);
    float2 f3 = __half22float2(*(__half2*)&w.w);
    fma2(aA, pk(f0.x, f0.y), hp0);
    fma2(aB, pk(f1.x, f1.y), hp1);
    fma2(aA, pk(f2.x, f2.y), hp2);
    fma2(aB, pk(f3.x, f3.y), hp3);
}
__device__ __forceinline__ uint4 pack4(float4 a, float4 b) {
    uint4 r; __half2 h;
    h = __floats2half2_rn(a.x, a.y); r.x = *(unsigned*)&h;
    h = __floats2half2_rn(a.z, a.w); r.y = *(unsigned*)&h;
    h = __floats2half2_rn(b.x, b.y); r.z = *(unsigned*)&h;
    h = __floats2half2_rn(b.z, b.w); r.w = *(unsigned*)&h;
    return r;
}

// ---------------- kernel 1: ih table GEMM + state/counter init --------------
__global__ __launch_bounds__(256) void tbl_kernel(
    const float* __restrict__ emb,     // [VOCAB, E]
    const float* __restrict__ w_ih,    // [G3, E]
    const float* __restrict__ b_ih,    // [G3]
    const float* __restrict__ b_hh)    // [G3]
{
    __shared__ float Es[32][33];
    __shared__ float Ws[64][33];
    const int tid = threadIdx.x;
    const int j0 = blockIdx.x * 64;
    const int v0 = blockIdx.y * 32;

    if (blockIdx.x == 0 && blockIdx.y == 0) {
        for (int i = tid; i < 2 * H_DIM; i += 256) ((float*)g_h)[i] = 0.f;
        if (tid == 0) g_cnt = 0u;
    }

    float acc[8] = {0.f, 0.f, 0.f, 0.f, 0.f, 0.f, 0.f, 0.f};
    const int jj = tid & 63;
    const int vb = (tid >> 6) * 8;

    for (int k0 = 0; k0 < E_DIM; k0 += 32) {
        __syncthreads();
        #pragma unroll
        for (int p = 0; p < 4; p++) {
            int idx = tid + p * 256;
            Es[idx >> 5][idx & 31] = emb[(size_t)(v0 + (idx >> 5)) * E_DIM + k0 + (idx & 31)];
        }
        #pragma unroll
        for (int p = 0; p < 8; p++) {
            int idx = tid + p * 256;
            Ws[idx >> 5][idx & 31] = w_ih[(size_t)(j0 + (idx >> 5)) * E_DIM + k0 + (idx & 31)];
        }
        __syncthreads();
        #pragma unroll
        for (int kk = 0; kk < 32; kk++) {
            float w = Ws[jj][kk];
            #pragma unroll
            for (int r = 0; r < 8; r++) acc[r] += w * Es[vb + r][kk];
        }
    }
    const int j = j0 + jj;
    float bias = b_ih[j] + ((j < 2 * H_DIM) ? b_hh[j] : 0.f);
    #pragma unroll
    for (int r = 0; r < 8; r++)
        g_tbl[(size_t)(v0 + vb + r) * G3 + j] = acc[r] + bias;
}

// ---------------- kernel 2: persistent GRU -----------------------------------
// Warp w of block b owns hidden unit u = b*14 + w. Weights for k in [0,1024)
// live in 48 registers/lane (packed half2); k in [1024,2048) in SMEM fp16.
// Dot products use packed fma.rn.f32x2. Grid sync = monotonic counter.
__global__ void __launch_bounds__(NTHR, 1) gru_kernel(
    const int*   __restrict__ x,
    const int*   __restrict__ lenp,
    const float* __restrict__ w_hh,    // [G3, H] fp32
    const float* __restrict__ b_hh,    // [G3]
    const float* __restrict__ dec_emb, // [128, E]
    float*       __restrict__ out,     // [E + H]
    int n_x)
{
    extern __shared__ __align__(16) unsigned char smem_raw[];
    __half* ws = (__half*)smem_raw;
    float*  hs = (float*)(smem_raw + HS_OFF);

    const int tid  = threadIdx.x;
    const int b    = blockIdx.x;
    const int lane = tid & 31;
    const int wid  = tid >> 5;

    const int u0 = b * UPB;
    int nu = H_DIM - u0;
    if (nu > UPB) nu = UPB;
    if (nu < 0) nu = 0;
    const bool writer = (wid < nu);
    const int u = u0 + wid;

    // ---- prologue: low-k halves -> registers, high-k halves -> SMEM ----
    uint4 wreg[12];   // [row*4 + c], c = 0..3 covers k in [0,1024)
    if (writer) {
        #pragma unroll
        for (int r = 0; r < 3; r++) {
            const float4* src = (const float4*)(w_hh + (size_t)(r * H_DIM + u) * H_DIM);
            #pragma unroll
            for (int c = 0; c < 4; c++) {
                float4 a = __ldcs(src + c * 64 + lane * 2);
                float4 q = __ldcs(src + c * 64 + lane * 2 + 1);
                wreg[r * 4 + c] = pack4(a, q);
            }
            uint4* dst = (uint4*)(ws + (size_t)(3 * wid + r) * WS2_HALFS);
            #pragma unroll
            for (int c = 0; c < 4; c++) {
                float4 a = __ldcs(src + 256 + c * 64 + lane * 2);
                float4 q = __ldcs(src + 256 + c * 64 + lane * 2 + 1);
                dst[c * 32 + lane] = pack4(a, q);
            }
        }
    }

    float bhn = 0.f;
    if (writer && lane == 0) bhn = __ldg(&b_hh[2 * H_DIM + u]);

    int steps = lenp[0] + 1;
    if (steps > n_x) steps = n_x;

    const uint4* wrow0 = (const uint4*)(ws + (size_t)(3 * wid)     * WS2_HALFS);
    const uint4* wrow1 = (const uint4*)(ws + (size_t)(3 * wid + 1) * WS2_HALFS);
    const uint4* wrow2 = (const uint4*)(ws + (size_t)(3 * wid + 2) * WS2_HALFS);
    const float4* hs4 = (const float4*)hs;

    unsigned target = 0;

    for (int t = 0; t < steps; ++t) {
        // hoisted step-t constants: L2 latency hides under the barrier poll
        float ih_r = 0.f, ih_z = 0.f, ih_n = 0.f;
        if (writer && lane == 0) {
            const int xt = __ldg(&x[t]);
            const float* __restrict__ tbl = g_tbl + (size_t)xt * G3;
            ih_r = __ldg(&tbl[u]);
            ih_z = __ldg(&tbl[u + H_DIM]);
            ih_n = __ldg(&tbl[u + 2 * H_DIM]);
        }

        // ---- wait: all blocks finished step t-1 ----
        if (tid == 0) {
            while (ld_acq(&g_cnt) < target) { }
        }
        __syncthreads();

        const int prev = t & 1;

        // ---- stage h(t-1) into SMEM ----
        {
            float4 v = __ldcg(((const float4*)g_h[prev]) + tid);
            ((float4*)hs)[tid] = v;
        }
        __syncthreads();

        if (writer) {
            unsigned long long a00 = 0ull, a01 = 0ull;
            unsigned long long a10 = 0ull, a11 = 0ull;
            unsigned long long a20 = 0ull, a21 = 0ull;
            #pragma unroll
            for (int c = 0; c < 8; c++) {
                float4 h0 = hs4[c * 64 + lane * 2];
                float4 h1 = hs4[c * 64 + lane * 2 + 1];
                unsigned long long hp0 = pk(h0.x, h0.y);
                unsigned long long hp1 = pk(h0.z, h0.w);
                unsigned long long hp2 = pk(h1.x, h1.y);
                unsigned long long hp3 = pk(h1.z, h1.w);
                uint4 w0 = (c < 4) ? wreg[0 * 4 + c] : wrow0[(c - 4) * 32 + lane];
                uint4 w1 = (c < 4) ? wreg[1 * 4 + c] : wrow1[(c - 4) * 32 + lane];
                uint4 w2 = (c < 4) ? wreg[2 * 4 + c] : wrow2[(c - 4) * 32 + lane];
                dotq(w0, hp0, hp1, hp2, hp3, a00, a01);
                dotq(w1, hp0, hp1, hp2, hp3, a10, a11);
                dotq(w2, hp0, hp1, hp2, hp3, a20, a21);
            }
            float2 s;
            float a0, a1, a2;
            s = unpk(a00); a0 = s.x + s.y;  s = unpk(a01); a0 += s.x + s.y;
            s = unpk(a10); a1 = s.x + s.y;  s = unpk(a11); a1 += s.x + s.y;
            s = unpk(a20); a2 = s.x + s.y;  s = unpk(a21); a2 += s.x + s.y;
            #pragma unroll
            for (int o = 16; o; o >>= 1) {
                a0 += __shfl_xor_sync(0xffffffffu, a0, o);
                a1 += __shfl_xor_sync(0xffffffffu, a1, o);
                a2 += __shfl_xor_sync(0xffffffffu, a2, o);
            }
            if (lane == 0) {
                float r = 1.f / (1.f + __expf(-(a0 + ih_r)));  // biases folded into tbl
                float z = 1.f / (1.f + __expf(-(a1 + ih_z)));
                float v = ih_n + r * (a2 + bhn);
                float e = __expf(2.f * v);
                float n = 1.f - __fdividef(2.f, e + 1.f);       // tanh(v)
                float hold = hs[u];
                __stcg(&g_h[prev ^ 1][u], (1.f - z) * n + z * hold);
            }
        }
        __syncthreads();

        // ---- arrive: one release-RED per block ----
        if (tid == 0) red_rel_add1(&g_cnt);
        target += NBLK;
    }

    if (b == 0) {
        if (tid == 0) {
            while (ld_acq(&g_cnt) < target) { }
        }
        __syncthreads();
        const int last = steps & 1;
        for (int i = tid; i < E_DIM; i += NTHR) out[i] = dec_emb[2 * E_DIM + i];
        for (int i = tid; i < H_DIM; i += NTHR) out[E_DIM + i] = __ldcg(&g_h[last][i]);
    }
}

// ---------------- launch ----------------------------------------------------
extern "C" void kernel_launch(void* const* d_in, const int* in_sizes, int n_in,
                              void* d_out, int out_size) {
    const int*   x       = (const int*)d_in[0];
    const int*   lenp    = (const int*)d_in[1];
    const float* enc_emb = (const float*)d_in[2];
    const float* w_ih    = (const float*)d_in[3];
    const float* w_hh    = (const float*)d_in[4];
    const float* b_ih    = (const float*)d_in[5];
    const float* b_hh    = (const float*)d_in[6];
    const float* dec_emb = (const float*)d_in[7];
    float* out = (float*)d_out;
    const int n_x = in_sizes[0];

    static int attr_set = 0;
    if (!attr_set) {
        cudaFuncSetAttribute(gru_kernel, cudaFuncAttributeMaxDynamicSharedMemorySize,
                             SMEM_TOTAL);
        attr_set = 1;
    }

    dim3 tgrid(G3 / 64, VOCAB / 32);   // 96 x 8
    tbl_kernel<<<tgrid, 256>>>(enc_emb, w_ih, b_ih, b_hh);
    gru_kernel<<<NBLK, NTHR, SMEM_TOTAL>>>(x, lenp, w_hh, b_hh, dec_emb, out, n_x);
}